// round 4
// baseline (speedup 1.0000x reference)
#include <cuda_runtime.h>
#include <math.h>

#define N_NODES 50000
#define TPB     256
#define GRID2   740          // edge kernel grid (148 * 5)

// Scratch (allocation-free __device__ globals). Zero-initialized at load;
// K2's last block resets them each launch -> deterministic across replays.
__device__ double   g_acc;
__device__ unsigned g_done;
__device__ float4   g_vtab[N_NODES * 8];   // per-(node, rel): (v0, v1, vb, 0)

__device__ __forceinline__ double block_reduce(double v) {
    __shared__ double sh[8];
    int lane = threadIdx.x & 31, wid = threadIdx.x >> 5;
    #pragma unroll
    for (int off = 16; off; off >>= 1) v += __shfl_down_sync(0xffffffffu, v, off);
    if (lane == 0) sh[wid] = v;
    __syncthreads();
    v = (threadIdx.x < (TPB >> 5)) ? sh[threadIdx.x] : 0.0;
    if (wid == 0) {
        #pragma unroll
        for (int off = 4; off; off >>= 1) v += __shfl_down_sync(0xffffffffu, v, off);
    }
    return v;
}

// ---------------------------------------------------------------------------
// K1: setup (per-block, in SMEM) + node pass.
// 16 weight rows per node instead of 28:
//   rows c*4+b (c<3,b<4): t[c][b][o] = sum_i hv[c][i]*bases[b,i,o]
//   rows 12..14:          sl[c][o]   = sum_i hv[c][i]*loop_w[i,o]
//   row  15:              h_bias
// Per node: p[c*4+b] = t-row . F[n]  ->  vtab[n,r].{x,y,z} = sum_b wc[r,b]*p[c*4+b]
// Self-loop readout: f.x*acc12 + f.y*acc13 + acc14 + acc15 -> g_acc.
// ---------------------------------------------------------------------------
__global__ void __launch_bounds__(TPB)
k_node(const float2* __restrict__ feats,
       const float* __restrict__ W_in, const float* __restrict__ b_in,
       const float* __restrict__ w_comp, const float* __restrict__ bases,
       const float* __restrict__ loop_w, const float* __restrict__ h_bias,
       const float* __restrict__ fcW)
{
    __shared__ float hv[3 * 64];
    __shared__ float4 ws[16 * 16];     // 16 rows of 64 floats, as float4
    __shared__ float wc[32];           // w_comp [8][4]
    float* wsf = (float*)ws;
    int tid = threadIdx.x;

    for (int i = tid; i < 192; i += TPB) {
        int c = i >> 6, o = i & 63;
        hv[i] = (c < 2) ? W_in[c * 64 + o] : b_in[o];
    }
    if (tid < 32) wc[tid] = w_comp[tid];
    __syncthreads();

    // rows 0..11: t[c][b]
    for (int k = tid; k < 768; k += TPB) {
        int c = k >> 8, b = (k >> 6) & 3, o = k & 63;
        float s = 0.f;
        #pragma unroll 8
        for (int i = 0; i < 64; i++)
            s += hv[c * 64 + i] * bases[b * 4096 + i * 64 + o];
        wsf[(c * 4 + b) * 64 + o] = s;
    }
    // rows 12..15
    for (int k = tid; k < 4 * 64; k += TPB) {
        int row = k >> 6, o = k & 63;
        float s;
        if (row < 3) {
            s = 0.f;
            #pragma unroll 8
            for (int i = 0; i < 64; i++)
                s += hv[row * 64 + i] * loop_w[i * 64 + o];
        } else {
            s = h_bias[o];
        }
        wsf[(12 + row) * 64 + o] = s;
    }
    __syncthreads();

    int n = blockIdx.x * TPB + tid;
    double contrib = 0.0;
    if (n < N_NODES) {
        const float4* F4 = (const float4*)(fcW + (size_t)n * 64);
        float acc[16];
        #pragma unroll
        for (int k = 0; k < 16; k++) acc[k] = 0.f;
        #pragma unroll 4
        for (int j = 0; j < 16; j++) {
            float4 f = F4[j];
            #pragma unroll
            for (int k = 0; k < 16; k++) {
                float4 w = ws[k * 16 + j];
                acc[k] += f.x * w.x + f.y * w.y + f.z * w.z + f.w * w.w;
            }
        }
        #pragma unroll
        for (int r = 0; r < 8; r++) {
            float4 v;
            v.x = wc[r*4]*acc[0] + wc[r*4+1]*acc[1] + wc[r*4+2]*acc[2]  + wc[r*4+3]*acc[3];
            v.y = wc[r*4]*acc[4] + wc[r*4+1]*acc[5] + wc[r*4+2]*acc[6]  + wc[r*4+3]*acc[7];
            v.z = wc[r*4]*acc[8] + wc[r*4+1]*acc[9] + wc[r*4+2]*acc[10] + wc[r*4+3]*acc[11];
            v.w = 0.f;
            g_vtab[n * 8 + r] = v;
        }
        float2 f = feats[n];
        contrib = (double)(f.x * acc[12] + f.y * acc[13] + acc[14] + acc[15]);
    }
    double bs = block_reduce(contrib);
    if (tid == 0) atomicAdd(&g_acc, bs);
}

// ---------------------------------------------------------------------------
// K2: edge pass + finalize (last-block-done). Streaming index loads (L1
// bypass via ldcs), L2-only vtab gathers (ldcg), L1-cached feats gathers.
// ---------------------------------------------------------------------------
__global__ void __launch_bounds__(TPB, 4)
k_edge(const float2* __restrict__ feats,
       const int* __restrict__ src, const int* __restrict__ dst,
       const int* __restrict__ et, const float* __restrict__ fc_b,
       int E, float* __restrict__ out)
{
    double contrib = 0.0;
    int nvec = E >> 2;
    const int4* s4p = (const int4*)src;
    const int4* d4p = (const int4*)dst;
    const int4* r4p = (const int4*)et;
    for (int i = blockIdx.x * TPB + threadIdx.x; i < nvec; i += GRID2 * TPB) {
        int4 s4 = __ldcs(&s4p[i]);
        int4 d4 = __ldcs(&d4p[i]);
        int4 r4 = __ldcs(&r4p[i]);
        float2 fa = feats[s4.x], fb = feats[s4.y], fc = feats[s4.z], fd = feats[s4.w];
        float4 va = __ldcg(&g_vtab[d4.x * 8 + r4.x]);
        float4 vb = __ldcg(&g_vtab[d4.y * 8 + r4.y]);
        float4 vc = __ldcg(&g_vtab[d4.z * 8 + r4.z]);
        float4 vd = __ldcg(&g_vtab[d4.w * 8 + r4.w]);
        float esum = fmaf(fa.x, va.x, fmaf(fa.y, va.y, va.z))
                   + fmaf(fb.x, vb.x, fmaf(fb.y, vb.y, vb.z))
                   + fmaf(fc.x, vc.x, fmaf(fc.y, vc.y, vc.z))
                   + fmaf(fd.x, vd.x, fmaf(fd.y, vd.y, vd.z));
        contrib += (double)esum;
    }
    for (int e = (nvec << 2) + blockIdx.x * TPB + threadIdx.x; e < E; e += GRID2 * TPB) {
        float2 f = feats[src[e]];
        float4 v = __ldcg(&g_vtab[dst[e] * 8 + et[e]]);
        contrib += (double)fmaf(f.x, v.x, fmaf(f.y, v.y, v.z));
    }

    double bs = block_reduce(contrib);
    if (threadIdx.x == 0) {
        atomicAdd(&g_acc, bs);
        __threadfence();
        unsigned d = atomicAdd(&g_done, 1u);
        if (d == GRID2 - 1) {
            double logit = atomicAdd(&g_acc, 0.0) + (double)fc_b[0];
            out[0] = (float)(1.0 / (1.0 + exp(-logit)));
            g_acc = 0.0;       // reset for next graph replay
            g_done = 0u;
        }
    }
}

extern "C" void kernel_launch(void* const* d_in, const int* in_sizes, int n_in,
                              void* d_out, int out_size) {
    const float* features = (const float*)d_in[0];
    const int*   src      = (const int*)d_in[1];
    const int*   dst      = (const int*)d_in[2];
    const int*   etype    = (const int*)d_in[3];
    const float* W_in     = (const float*)d_in[4];
    const float* b_in     = (const float*)d_in[5];
    const float* w_comp   = (const float*)d_in[6];
    const float* bases    = (const float*)d_in[7];
    const float* loop_w   = (const float*)d_in[8];
    const float* h_bias   = (const float*)d_in[9];
    const float* fc_W     = (const float*)d_in[10];
    const float* fc_b     = (const float*)d_in[11];
    int E = in_sizes[1];

    k_node<<<(N_NODES + TPB - 1) / TPB, TPB>>>((const float2*)features,
                                               W_in, b_in, w_comp, bases,
                                               loop_w, h_bias, fc_W);
    k_edge<<<GRID2, TPB>>>((const float2*)features, src, dst, etype,
                           fc_b, E, (float*)d_out);
}

// round 5
// speedup vs baseline: 1.7284x; 1.7284x over previous
#include <cuda_runtime.h>
#include <math.h>

#define N_NODES 50000
#define TPB_N   128
#define TPB_E   256
#define GRID_E  592          // 148 SMs * 4 CTAs -> exactly one wave

// Scratch (allocation-free __device__ globals). Zero-initialized at load;
// K2's last block resets counters each launch -> deterministic across replays.
__device__ double   g_acc;
__device__ unsigned g_done;
__device__ float    g_Wt[16 * 64];         // 16 weight rows (t[c][b], sl[c], h_bias)
__device__ float    g_wc[32];              // w_comp copy
__device__ float4   g_vtab[N_NODES * 8];   // per-(node, rel): (v0, v1, vb, 0)

// ---------------------------------------------------------------------------
// K0: setup. Build 16 length-64 rows:
//   rows c*4+b (c<3,b<4): t[c][b][o] = sum_i hv[c][i]*bases[b,i,o]
//   rows 12..14:          sl[c][o]   = sum_i hv[c][i]*loop_w[i,o]
//   row  15:              h_bias
// hv[0]=W_in[0,:], hv[1]=W_in[1,:], hv[2]=b_in.
// ---------------------------------------------------------------------------
__global__ void k_setup(const float* __restrict__ W_in, const float* __restrict__ b_in,
                        const float* __restrict__ w_comp, const float* __restrict__ bases,
                        const float* __restrict__ loop_w, const float* __restrict__ h_bias) {
    __shared__ float hv[3 * 64];
    int tid = threadIdx.x;
    for (int i = tid; i < 192; i += 256) {
        int c = i >> 6, o = i & 63;
        hv[i] = (c < 2) ? W_in[c * 64 + o] : b_in[o];
    }
    if (tid < 32) g_wc[tid] = w_comp[tid];
    __syncthreads();

    for (int k = tid; k < 768; k += 256) {     // rows 0..11
        int c = k >> 8, b = (k >> 6) & 3, o = k & 63;
        float s = 0.f;
        #pragma unroll 16
        for (int i = 0; i < 64; i++)
            s += hv[c * 64 + i] * bases[b * 4096 + i * 64 + o];
        g_Wt[(c * 4 + b) * 64 + o] = s;
    }
    for (int k = tid; k < 256; k += 256) {     // rows 12..15
        int row = k >> 6, o = k & 63;
        float s;
        if (row < 3) {
            s = 0.f;
            #pragma unroll 16
            for (int i = 0; i < 64; i++)
                s += hv[row * 64 + i] * loop_w[i * 64 + o];
        } else {
            s = h_bias[o];
        }
        g_Wt[(12 + row) * 64 + o] = s;
    }
}

__device__ __forceinline__ double block_reduce(double v, int nthreads) {
    __shared__ double sh[8];
    int lane = threadIdx.x & 31, wid = threadIdx.x >> 5;
    #pragma unroll
    for (int off = 16; off; off >>= 1) v += __shfl_down_sync(0xffffffffu, v, off);
    if (lane == 0) sh[wid] = v;
    __syncthreads();
    int nw = nthreads >> 5;
    v = (threadIdx.x < nw) ? sh[threadIdx.x] : 0.0;
    if (wid == 0) {
        #pragma unroll
        for (int off = 4; off; off >>= 1) v += __shfl_down_sync(0xffffffffu, v, off);
    }
    return v;
}

// ---------------------------------------------------------------------------
// K1: node pass. Thread-per-node, 16 accumulators:
//   p[c*4+b] = t-row . F[n]  ->  vtab[n,r].{x,y,z} = sum_b wc[r,b]*p[..]
// Self-loop readout: f.x*p12 + f.y*p13 + p14 + p15 -> g_acc.
// ---------------------------------------------------------------------------
__global__ void __launch_bounds__(TPB_N)
k_node(const float2* __restrict__ feats, const float* __restrict__ fcW)
{
    __shared__ float4 ws[16 * 16];
    __shared__ float wc[32];
    int tid = threadIdx.x;
    for (int i = tid; i < 16 * 16; i += TPB_N)
        ws[i] = ((const float4*)g_Wt)[i];
    if (tid < 32) wc[tid] = g_wc[tid];
    __syncthreads();

    int n = blockIdx.x * TPB_N + tid;
    double contrib = 0.0;
    if (n < N_NODES) {
        const float4* F4 = (const float4*)(fcW + (size_t)n * 64);
        float acc[16];
        #pragma unroll
        for (int k = 0; k < 16; k++) acc[k] = 0.f;
        #pragma unroll 4
        for (int j = 0; j < 16; j++) {
            float4 f = F4[j];
            #pragma unroll
            for (int k = 0; k < 16; k++) {
                float4 w = ws[k * 16 + j];
                acc[k] += f.x * w.x + f.y * w.y + f.z * w.z + f.w * w.w;
            }
        }
        #pragma unroll
        for (int r = 0; r < 8; r++) {
            float4 v;
            v.x = wc[r*4]*acc[0] + wc[r*4+1]*acc[1] + wc[r*4+2]*acc[2]  + wc[r*4+3]*acc[3];
            v.y = wc[r*4]*acc[4] + wc[r*4+1]*acc[5] + wc[r*4+2]*acc[6]  + wc[r*4+3]*acc[7];
            v.z = wc[r*4]*acc[8] + wc[r*4+1]*acc[9] + wc[r*4+2]*acc[10] + wc[r*4+3]*acc[11];
            v.w = 0.f;
            g_vtab[n * 8 + r] = v;
        }
        float2 f = feats[n];
        contrib = (double)(f.x * acc[12] + f.y * acc[13] + acc[14] + acc[15]);
    }
    double bs = block_reduce(contrib, TPB_N);
    if (tid == 0) atomicAdd(&g_acc, bs);
}

// ---------------------------------------------------------------------------
// K2: edge pass + finalize. Default cache policy everywhere; exactly one
// wave (592 blocks @ 4 CTAs/SM); 4 edges per iteration via int4 indices.
// ---------------------------------------------------------------------------
__global__ void __launch_bounds__(TPB_E, 4)
k_edge(const float2* __restrict__ feats,
       const int* __restrict__ src, const int* __restrict__ dst,
       const int* __restrict__ et, const float* __restrict__ fc_b,
       int E, float* __restrict__ out)
{
    double contrib = 0.0;
    int nvec = E >> 2;
    const int4* s4p = (const int4*)src;
    const int4* d4p = (const int4*)dst;
    const int4* r4p = (const int4*)et;
    for (int i = blockIdx.x * TPB_E + threadIdx.x; i < nvec; i += GRID_E * TPB_E) {
        int4 s4 = s4p[i], d4 = d4p[i], r4 = r4p[i];
        float2 fa = feats[s4.x], fb = feats[s4.y], fc = feats[s4.z], fd = feats[s4.w];
        float4 va = g_vtab[d4.x * 8 + r4.x];
        float4 vb = g_vtab[d4.y * 8 + r4.y];
        float4 vc = g_vtab[d4.z * 8 + r4.z];
        float4 vd = g_vtab[d4.w * 8 + r4.w];
        float esum = fmaf(fa.x, va.x, fmaf(fa.y, va.y, va.z))
                   + fmaf(fb.x, vb.x, fmaf(fb.y, vb.y, vb.z))
                   + fmaf(fc.x, vc.x, fmaf(fc.y, vc.y, vc.z))
                   + fmaf(fd.x, vd.x, fmaf(fd.y, vd.y, vd.z));
        contrib += (double)esum;
    }
    for (int e = (nvec << 2) + blockIdx.x * TPB_E + threadIdx.x; e < E; e += GRID_E * TPB_E) {
        float2 f = feats[src[e]];
        float4 v = g_vtab[dst[e] * 8 + et[e]];
        contrib += (double)fmaf(f.x, v.x, fmaf(f.y, v.y, v.z));
    }

    double bs = block_reduce(contrib, TPB_E);
    if (threadIdx.x == 0) {
        atomicAdd(&g_acc, bs);
        __threadfence();
        unsigned d = atomicAdd(&g_done, 1u);
        if (d == GRID_E - 1) {
            double logit = atomicAdd(&g_acc, 0.0) + (double)fc_b[0];
            out[0] = (float)(1.0 / (1.0 + exp(-logit)));
            g_acc = 0.0;       // reset for next graph replay
            g_done = 0u;
        }
    }
}

extern "C" void kernel_launch(void* const* d_in, const int* in_sizes, int n_in,
                              void* d_out, int out_size) {
    const float* features = (const float*)d_in[0];
    const int*   src      = (const int*)d_in[1];
    const int*   dst      = (const int*)d_in[2];
    const int*   etype    = (const int*)d_in[3];
    const float* W_in     = (const float*)d_in[4];
    const float* b_in     = (const float*)d_in[5];
    const float* w_comp   = (const float*)d_in[6];
    const float* bases    = (const float*)d_in[7];
    const float* loop_w   = (const float*)d_in[8];
    const float* h_bias   = (const float*)d_in[9];
    const float* fc_W     = (const float*)d_in[10];
    const float* fc_b     = (const float*)d_in[11];
    int E = in_sizes[1];

    k_setup<<<1, 256>>>(W_in, b_in, w_comp, bases, loop_w, h_bias);
    k_node<<<(N_NODES + TPB_N - 1) / TPB_N, TPB_N>>>((const float2*)features, fc_W);
    k_edge<<<GRID_E, TPB_E>>>((const float2*)features, src, dst, etype,
                              fc_b, E, (float*)d_out);
}

// round 6
// speedup vs baseline: 1.9652x; 1.1370x over previous
#include <cuda_runtime.h>
#include <math.h>

#define N_NODES 50000
#define TPB_N   128
#define TPB_E   256
#define GRID_E  592          // 148 SMs * 4 CTAs -> exactly one wave

// Scratch (allocation-free __device__ globals). Zero-initialized at load;
// K2's last block resets counters each launch -> deterministic across replays.
__device__ double   g_acc;
__device__ unsigned g_done;
__device__ float    g_Wt[16 * 64];         // 16 weight rows (t[c][b], sl[c], h_bias)
__device__ float    g_wc[32];              // w_comp copy
__device__ float4   g_vtab[N_NODES * 8];   // per-(node, rel): (v0, v1, vb, 0)

// ---------------------------------------------------------------------------
// K0: setup, parallelized across 16 blocks (one per output row of g_Wt).
//   rows c*4+b (c<3,b<4): t[c][b][o] = sum_i hv[c][i]*bases[b,i,o]
//   rows 12..14:          sl[c][o]   = sum_i hv[c][i]*loop_w[i,o]
//   row  15:              h_bias
// hv[0]=W_in[0,:], hv[1]=W_in[1,:], hv[2]=b_in.
// Block = 64 threads; thread o computes one output element (coalesced reads).
// ---------------------------------------------------------------------------
__global__ void __launch_bounds__(64)
k_setup(const float* __restrict__ W_in, const float* __restrict__ b_in,
        const float* __restrict__ w_comp, const float* __restrict__ bases,
        const float* __restrict__ loop_w, const float* __restrict__ h_bias) {
    __shared__ float hv[64];
    int o   = threadIdx.x;
    int row = blockIdx.x;

    if (row == 0 && o < 32) g_wc[o] = w_comp[o];

    if (row == 15) {                 // h_bias row: trivial copy
        g_Wt[15 * 64 + o] = h_bias[o];
        return;
    }

    int c, b;
    const float* M;                  // matrix to contract: bases[b] or loop_w
    if (row < 12) { c = row >> 2; b = row & 3; M = bases + b * 4096; }
    else          { c = row - 12;              M = loop_w; }

    hv[o] = (c < 2) ? W_in[c * 64 + o] : b_in[o];
    __syncthreads();

    float s = 0.f;
    #pragma unroll 16
    for (int i = 0; i < 64; i++)
        s += hv[i] * __ldg(&M[i * 64 + o]);
    g_Wt[row * 64 + o] = s;
}

__device__ __forceinline__ double block_reduce(double v, int nthreads) {
    __shared__ double sh[8];
    int lane = threadIdx.x & 31, wid = threadIdx.x >> 5;
    #pragma unroll
    for (int off = 16; off; off >>= 1) v += __shfl_down_sync(0xffffffffu, v, off);
    if (lane == 0) sh[wid] = v;
    __syncthreads();
    int nw = nthreads >> 5;
    v = (threadIdx.x < nw) ? sh[threadIdx.x] : 0.0;
    if (wid == 0) {
        #pragma unroll
        for (int off = 4; off; off >>= 1) v += __shfl_down_sync(0xffffffffu, v, off);
    }
    return v;
}

// ---------------------------------------------------------------------------
// K1: node pass. Thread-per-node, 16 accumulators:
//   p[c*4+b] = t-row . F[n]  ->  vtab[n,r].{x,y,z} = sum_b wc[r,b]*p[..]
// Self-loop readout: f.x*p12 + f.y*p13 + p14 + p15 -> g_acc.
// ---------------------------------------------------------------------------
__global__ void __launch_bounds__(TPB_N)
k_node(const float2* __restrict__ feats, const float* __restrict__ fcW)
{
    __shared__ float4 ws[16 * 16];
    __shared__ float wc[32];
    int tid = threadIdx.x;
    for (int i = tid; i < 16 * 16; i += TPB_N)
        ws[i] = ((const float4*)g_Wt)[i];
    if (tid < 32) wc[tid] = g_wc[tid];
    __syncthreads();

    int n = blockIdx.x * TPB_N + tid;
    double contrib = 0.0;
    if (n < N_NODES) {
        const float4* F4 = (const float4*)(fcW + (size_t)n * 64);
        float acc[16];
        #pragma unroll
        for (int k = 0; k < 16; k++) acc[k] = 0.f;
        #pragma unroll 4
        for (int j = 0; j < 16; j++) {
            float4 f = F4[j];
            #pragma unroll
            for (int k = 0; k < 16; k++) {
                float4 w = ws[k * 16 + j];
                acc[k] += f.x * w.x + f.y * w.y + f.z * w.z + f.w * w.w;
            }
        }
        #pragma unroll
        for (int r = 0; r < 8; r++) {
            float4 v;
            v.x = wc[r*4]*acc[0] + wc[r*4+1]*acc[1] + wc[r*4+2]*acc[2]  + wc[r*4+3]*acc[3];
            v.y = wc[r*4]*acc[4] + wc[r*4+1]*acc[5] + wc[r*4+2]*acc[6]  + wc[r*4+3]*acc[7];
            v.z = wc[r*4]*acc[8] + wc[r*4+1]*acc[9] + wc[r*4+2]*acc[10] + wc[r*4+3]*acc[11];
            v.w = 0.f;
            g_vtab[n * 8 + r] = v;
        }
        float2 f = feats[n];
        contrib = (double)(f.x * acc[12] + f.y * acc[13] + acc[14] + acc[15]);
    }
    double bs = block_reduce(contrib, TPB_N);
    if (tid == 0) atomicAdd(&g_acc, bs);
}

// ---------------------------------------------------------------------------
// K2: edge pass + finalize. Default cache policy everywhere; exactly one
// wave (592 blocks @ 4 CTAs/SM); 4 edges per iteration via int4 indices.
// ---------------------------------------------------------------------------
__global__ void __launch_bounds__(TPB_E, 4)
k_edge(const float2* __restrict__ feats,
       const int* __restrict__ src, const int* __restrict__ dst,
       const int* __restrict__ et, const float* __restrict__ fc_b,
       int E, float* __restrict__ out)
{
    double contrib = 0.0;
    int nvec = E >> 2;
    const int4* s4p = (const int4*)src;
    const int4* d4p = (const int4*)dst;
    const int4* r4p = (const int4*)et;
    for (int i = blockIdx.x * TPB_E + threadIdx.x; i < nvec; i += GRID_E * TPB_E) {
        int4 s4 = s4p[i], d4 = d4p[i], r4 = r4p[i];
        float2 fa = feats[s4.x], fb = feats[s4.y], fc = feats[s4.z], fd = feats[s4.w];
        float4 va = g_vtab[d4.x * 8 + r4.x];
        float4 vb = g_vtab[d4.y * 8 + r4.y];
        float4 vc = g_vtab[d4.z * 8 + r4.z];
        float4 vd = g_vtab[d4.w * 8 + r4.w];
        float esum = fmaf(fa.x, va.x, fmaf(fa.y, va.y, va.z))
                   + fmaf(fb.x, vb.x, fmaf(fb.y, vb.y, vb.z))
                   + fmaf(fc.x, vc.x, fmaf(fc.y, vc.y, vc.z))
                   + fmaf(fd.x, vd.x, fmaf(fd.y, vd.y, vd.z));
        contrib += (double)esum;
    }
    for (int e = (nvec << 2) + blockIdx.x * TPB_E + threadIdx.x; e < E; e += GRID_E * TPB_E) {
        float2 f = feats[src[e]];
        float4 v = g_vtab[dst[e] * 8 + et[e]];
        contrib += (double)fmaf(f.x, v.x, fmaf(f.y, v.y, v.z));
    }

    double bs = block_reduce(contrib, TPB_E);
    if (threadIdx.x == 0) {
        atomicAdd(&g_acc, bs);
        __threadfence();
        unsigned d = atomicAdd(&g_done, 1u);
        if (d == GRID_E - 1) {
            double logit = atomicAdd(&g_acc, 0.0) + (double)fc_b[0];
            out[0] = (float)(1.0 / (1.0 + exp(-logit)));
            g_acc = 0.0;       // reset for next graph replay
            g_done = 0u;
        }
    }
}

extern "C" void kernel_launch(void* const* d_in, const int* in_sizes, int n_in,
                              void* d_out, int out_size) {
    const float* features = (const float*)d_in[0];
    const int*   src      = (const int*)d_in[1];
    const int*   dst      = (const int*)d_in[2];
    const int*   etype    = (const int*)d_in[3];
    const float* W_in     = (const float*)d_in[4];
    const float* b_in     = (const float*)d_in[5];
    const float* w_comp   = (const float*)d_in[6];
    const float* bases    = (const float*)d_in[7];
    const float* loop_w   = (const float*)d_in[8];
    const float* h_bias   = (const float*)d_in[9];
    const float* fc_W     = (const float*)d_in[10];
    const float* fc_b     = (const float*)d_in[11];
    int E = in_sizes[1];

    k_setup<<<16, 64>>>(W_in, b_in, w_comp, bases, loop_w, h_bias);
    k_node<<<(N_NODES + TPB_N - 1) / TPB_N, TPB_N>>>((const float2*)features, fc_W);
    k_edge<<<GRID_E, TPB_E>>>((const float2*)features, src, dst, etype,
                              fc_b, E, (float*)d_out);
}

// round 7
// speedup vs baseline: 2.1075x; 1.0724x over previous
#include <cuda_runtime.h>
#include <math.h>

#define N_NODES 50000
#define TPB_N   128
#define TPB_E   256
#define GRID_E  592          // 148 SMs * 4 CTAs -> exactly one wave

// Scratch (allocation-free __device__ globals). Zero-initialized at load;
// K2's last block resets counters each launch -> deterministic across replays.
__device__ double   g_acc;
__device__ unsigned g_done;
__device__ float    g_Wt[16 * 64];          // 16 weight rows (t[c][b], sl[c], h_bias)
__device__ float    g_wc[32];               // w_comp copy
__device__ float4   g_vtab[8 * N_NODES];    // [rel][node]: (v0, v1, vb, 0)

// ---------------------------------------------------------------------------
// K0: setup. 16 blocks (one per g_Wt row) x 256 threads.
// Thread (o = tid&63, q = tid>>6) accumulates i = q*16 .. q*16+15;
// 4 partials reduced deterministically in smem.
//   rows c*4+b (c<3,b<4): t[c][b][o] = sum_i hv[c][i]*bases[b,i,o]
//   rows 12..14:          sl[c][o]   = sum_i hv[c][i]*loop_w[i,o]
//   row  15:              h_bias
// ---------------------------------------------------------------------------
__global__ void __launch_bounds__(256)
k_setup(const float* __restrict__ W_in, const float* __restrict__ b_in,
        const float* __restrict__ w_comp, const float* __restrict__ bases,
        const float* __restrict__ loop_w, const float* __restrict__ h_bias) {
    __shared__ float hv[64];
    __shared__ float part[4][64];
    int tid = threadIdx.x;
    int o = tid & 63, q = tid >> 6;
    int row = blockIdx.x;

    if (row == 0 && tid < 32) g_wc[tid] = w_comp[tid];

    if (row == 15) {
        if (tid < 64) g_Wt[15 * 64 + tid] = h_bias[tid];
        return;
    }

    int c;
    const float* M;
    if (row < 12) { c = row >> 2; M = bases + (row & 3) * 4096; }
    else          { c = row - 12; M = loop_w; }

    if (tid < 64) hv[tid] = (c < 2) ? W_in[c * 64 + tid] : b_in[tid];
    __syncthreads();

    float s = 0.f;
    int i0 = q * 16;
    #pragma unroll 16
    for (int i = 0; i < 16; i++)
        s += hv[i0 + i] * __ldg(&M[(i0 + i) * 64 + o]);
    part[q][o] = s;
    __syncthreads();

    if (tid < 64) {
        // Deterministic order matching the original serial i = 0..63 sum:
        float r = ((part[0][tid] + part[1][tid]) + part[2][tid]) + part[3][tid];
        g_Wt[row * 64 + tid] = r;
    }
}

__device__ __forceinline__ double block_reduce(double v, int nthreads) {
    __shared__ double sh[8];
    int lane = threadIdx.x & 31, wid = threadIdx.x >> 5;
    #pragma unroll
    for (int off = 16; off; off >>= 1) v += __shfl_down_sync(0xffffffffu, v, off);
    if (lane == 0) sh[wid] = v;
    __syncthreads();
    int nw = nthreads >> 5;
    v = (threadIdx.x < nw) ? sh[threadIdx.x] : 0.0;
    if (wid == 0) {
        #pragma unroll
        for (int off = 4; off; off >>= 1) v += __shfl_down_sync(0xffffffffu, v, off);
    }
    return v;
}

// ---------------------------------------------------------------------------
// K1: node pass. fcW tile staged through SMEM (coalesced gmem loads, padded
// rows for bank-conflict control). vtab stored [rel][node] -> coalesced
// 512B warp stores. 16 accumulators per node:
//   p[c*4+b] = t-row . F[n]  ->  vtab[r][n].{x,y,z} = sum_b wc[r,b]*p[..]
// Self-loop readout: f.x*p12 + f.y*p13 + p14 + p15 -> g_acc.
// ---------------------------------------------------------------------------
#define TSTRIDE 68           // floats per padded tile row (16B-aligned rows)

__global__ void __launch_bounds__(TPB_N)
k_node(const float2* __restrict__ feats, const float* __restrict__ fcW)
{
    __shared__ float  tile[TPB_N * TSTRIDE];   // 128 rows x 68 floats = 34 KB
    __shared__ float4 ws[16 * 16];
    __shared__ float  wc[32];
    int tid = threadIdx.x;
    for (int i = tid; i < 16 * 16; i += TPB_N)
        ws[i] = ((const float4*)g_Wt)[i];
    if (tid < 32) wc[tid] = g_wc[tid];

    int nbase = blockIdx.x * TPB_N;
    int nblk  = min(TPB_N, N_NODES - nbase);   // nodes in this block

    // Coalesced load: 16*nblk float4s, lane-consecutive in gmem.
    const float4* src4 = (const float4*)(fcW + (size_t)nbase * 64);
    int total4 = nblk * 16;
    for (int idx = tid; idx < total4; idx += TPB_N) {
        float4 f = src4[idx];
        int node = idx >> 4, j4 = idx & 15;
        ((float4*)(tile + node * TSTRIDE))[j4] = f;
    }
    __syncthreads();

    double contrib = 0.0;
    if (tid < nblk) {
        int n = nbase + tid;
        const float4* F4 = (const float4*)(tile + tid * TSTRIDE);
        float acc[16];
        #pragma unroll
        for (int k = 0; k < 16; k++) acc[k] = 0.f;
        #pragma unroll 4
        for (int j = 0; j < 16; j++) {
            float4 f = F4[j];
            #pragma unroll
            for (int k = 0; k < 16; k++) {
                float4 w = ws[k * 16 + j];
                acc[k] += f.x * w.x + f.y * w.y + f.z * w.z + f.w * w.w;
            }
        }
        #pragma unroll
        for (int r = 0; r < 8; r++) {
            float4 v;
            v.x = wc[r*4]*acc[0] + wc[r*4+1]*acc[1] + wc[r*4+2]*acc[2]  + wc[r*4+3]*acc[3];
            v.y = wc[r*4]*acc[4] + wc[r*4+1]*acc[5] + wc[r*4+2]*acc[6]  + wc[r*4+3]*acc[7];
            v.z = wc[r*4]*acc[8] + wc[r*4+1]*acc[9] + wc[r*4+2]*acc[10] + wc[r*4+3]*acc[11];
            v.w = 0.f;
            g_vtab[r * N_NODES + n] = v;     // lane-coalesced per r
        }
        float2 f = feats[n];
        contrib = (double)(f.x * acc[12] + f.y * acc[13] + acc[14] + acc[15]);
    }
    double bs = block_reduce(contrib, TPB_N);
    if (tid == 0) atomicAdd(&g_acc, bs);
}

// ---------------------------------------------------------------------------
// K2: edge pass + finalize. Default cache policy; exactly one wave
// (592 blocks @ 4 CTAs/SM); 4 edges per iteration via int4 indices.
// vtab indexed [rel][node].
// ---------------------------------------------------------------------------
__global__ void __launch_bounds__(TPB_E, 4)
k_edge(const float2* __restrict__ feats,
       const int* __restrict__ src, const int* __restrict__ dst,
       const int* __restrict__ et, const float* __restrict__ fc_b,
       int E, float* __restrict__ out)
{
    double contrib = 0.0;
    int nvec = E >> 2;
    const int4* s4p = (const int4*)src;
    const int4* d4p = (const int4*)dst;
    const int4* r4p = (const int4*)et;
    for (int i = blockIdx.x * TPB_E + threadIdx.x; i < nvec; i += GRID_E * TPB_E) {
        int4 s4 = s4p[i], d4 = d4p[i], r4 = r4p[i];
        float2 fa = feats[s4.x], fb = feats[s4.y], fc = feats[s4.z], fd = feats[s4.w];
        float4 va = g_vtab[r4.x * N_NODES + d4.x];
        float4 vb = g_vtab[r4.y * N_NODES + d4.y];
        float4 vc = g_vtab[r4.z * N_NODES + d4.z];
        float4 vd = g_vtab[r4.w * N_NODES + d4.w];
        float esum = fmaf(fa.x, va.x, fmaf(fa.y, va.y, va.z))
                   + fmaf(fb.x, vb.x, fmaf(fb.y, vb.y, vb.z))
                   + fmaf(fc.x, vc.x, fmaf(fc.y, vc.y, vc.z))
                   + fmaf(fd.x, vd.x, fmaf(fd.y, vd.y, vd.z));
        contrib += (double)esum;
    }
    for (int e = (nvec << 2) + blockIdx.x * TPB_E + threadIdx.x; e < E; e += GRID_E * TPB_E) {
        float2 f = feats[src[e]];
        float4 v = g_vtab[et[e] * N_NODES + dst[e]];
        contrib += (double)fmaf(f.x, v.x, fmaf(f.y, v.y, v.z));
    }

    double bs = block_reduce(contrib, TPB_E);
    if (threadIdx.x == 0) {
        atomicAdd(&g_acc, bs);
        __threadfence();
        unsigned d = atomicAdd(&g_done, 1u);
        if (d == GRID_E - 1) {
            double logit = atomicAdd(&g_acc, 0.0) + (double)fc_b[0];
            out[0] = (float)(1.0 / (1.0 + exp(-logit)));
            g_acc = 0.0;       // reset for next graph replay
            g_done = 0u;
        }
    }
}

extern "C" void kernel_launch(void* const* d_in, const int* in_sizes, int n_in,
                              void* d_out, int out_size) {
    const float* features = (const float*)d_in[0];
    const int*   src      = (const int*)d_in[1];
    const int*   dst      = (const int*)d_in[2];
    const int*   etype    = (const int*)d_in[3];
    const float* W_in     = (const float*)d_in[4];
    const float* b_in     = (const float*)d_in[5];
    const float* w_comp   = (const float*)d_in[6];
    const float* bases    = (const float*)d_in[7];
    const float* loop_w   = (const float*)d_in[8];
    const float* h_bias   = (const float*)d_in[9];
    const float* fc_W     = (const float*)d_in[10];
    const float* fc_b     = (const float*)d_in[11];
    int E = in_sizes[1];

    k_setup<<<16, 256>>>(W_in, b_in, w_comp, bases, loop_w, h_bias);
    k_node<<<(N_NODES + TPB_N - 1) / TPB_N, TPB_N>>>((const float2*)features, fc_W);
    k_edge<<<GRID_E, TPB_E>>>((const float2*)features, src, dst, etype,
                              fc_b, E, (float*)d_out);
}